// round 2
// baseline (speedup 1.0000x reference)
#include <cuda_runtime.h>
#include <cuda_bf16.h>
#include <math.h>
#include <stdint.h>

// Model dims
#define LNUM 12
#define DMODEL 768
#define NHEAD 6
#define HDIM 128
#define FFDIM 3072
#define VOCAB 65536
#define SEQ 2048
#define EPSV 1e-5f
#define CAPV 30.0f

// ---------------- scratch (static device arrays; no allocation) -------------
__device__ float g_x[SEQ * DMODEL];       // residual stream
__device__ float g_n[SEQ * DMODEL];       // normed / attention-out (reused)
__device__ float g_q[SEQ * DMODEL];
__device__ float g_k[SEQ * DMODEL];
__device__ float g_v[SEQ * DMODEL];
__device__ float g_big[SEQ * FFDIM];      // qkv out (2304<=3072) and MLP hidden
__device__ float g_rowsum[SEQ];
__device__ float g_tl[SEQ];

// ---------------- helpers ----------------------------------------------------
__device__ __forceinline__ float blockReduceSum(float v) {
    __shared__ float sh[32];
    __syncthreads();                       // protect sh reuse across calls
    int lane = threadIdx.x & 31, wid = threadIdx.x >> 5;
    #pragma unroll
    for (int o = 16; o; o >>= 1) v += __shfl_xor_sync(0xffffffffu, v, o);
    if (lane == 0) sh[wid] = v;
    __syncthreads();
    int nw = blockDim.x >> 5;
    v = (threadIdx.x < nw) ? sh[threadIdx.x] : 0.f;
    if (wid == 0) {
        #pragma unroll
        for (int o = 16; o; o >>= 1) v += __shfl_xor_sync(0xffffffffu, v, o);
        if (lane == 0) sh[0] = v;
    }
    __syncthreads();
    return sh[0];
}

// ---------------- elementwise kernels ----------------------------------------
__global__ void embed_kernel(const int* __restrict__ idx,
                             const float* __restrict__ emb) {
    int t = blockIdx.x;
    int row = idx[t];
    const float* src = emb + (size_t)row * DMODEL;
    for (int i = threadIdx.x; i < DMODEL; i += blockDim.x)
        g_x[t * DMODEL + i] = src[i];
}

__global__ void rmsnorm_kernel(const float* __restrict__ x,
                               const float* __restrict__ w,
                               float* __restrict__ o) {
    int t = blockIdx.x;
    const float* xr = x + (size_t)t * DMODEL;
    float s = 0.f;
    for (int i = threadIdx.x; i < DMODEL; i += blockDim.x) {
        float v = xr[i];
        s += v * v;
    }
    s = blockReduceSum(s);
    float r = rsqrtf(s / (float)DMODEL + EPSV);
    for (int i = threadIdx.x; i < DMODEL; i += blockDim.x)
        o[t * DMODEL + i] = xr[i] * r * w[i];
}

// Per (t, head): q/k head-RMSNorm + RoPE, scatter to g_q/g_k/g_v. 128 threads.
__global__ void rope_kernel(const float* __restrict__ qkv,
                            const float* __restrict__ qw,
                            const float* __restrict__ kw) {
    int t = blockIdx.x, h = blockIdx.y, d = threadIdx.x;
    const float* base = qkv + (size_t)t * (3 * DMODEL);
    float qd = base[h * HDIM + d];
    float kd = base[DMODEL + h * HDIM + d];
    float vd = base[2 * DMODEL + h * HDIM + d];
    float qs = blockReduceSum(qd * qd);
    float ks = blockReduceSum(kd * kd);
    float qn = qd * rsqrtf(qs / (float)HDIM + EPSV) * qw[d];
    float kn = kd * rsqrtf(ks / (float)HDIM + EPSV) * kw[d];
    __shared__ float sq[HDIM], sk[HDIM];
    sq[d] = qn; sk[d] = kn;
    __syncthreads();
    float expo = -(float)((d & 63) * 2) / (float)HDIM;
    float invf = expf(expo * logf(10000.f));
    float ang = (float)t * invf;
    float c = cosf(ang), s = sinf(ang);
    float qr = (d < 64) ? -sq[d + 64] : sq[d - 64];
    float kr = (d < 64) ? -sk[d + 64] : sk[d - 64];
    size_t oidx = (size_t)t * DMODEL + h * HDIM + d;
    g_q[oidx] = qn * c + qr * s;
    g_k[oidx] = kn * c + kr * s;
    g_v[oidx] = vd;
}

// ---------------- attention: warp-per-query, online softmax ------------------
// grid (SEQ/8, NHEAD), 256 threads (8 warps)
__global__ void attn_kernel() {
    const int h = blockIdx.y;
    const int qbase = blockIdx.x * 8;
    const int warp = threadIdx.x >> 5, lane = threadIdx.x & 31;
    const int qi = qbase + warp;
    __shared__ float Ks[32][HDIM];
    __shared__ float Vs[32][HDIM];
    float ql[4];
    #pragma unroll
    for (int j = 0; j < 4; j++)
        ql[j] = g_q[(size_t)qi * DMODEL + h * HDIM + lane + 32 * j];
    float m = -1e30f, l = 0.f;
    float acc[4] = {0.f, 0.f, 0.f, 0.f};
    int ntiles = (qbase + 8 + 31) >> 5;
    for (int tb = 0; tb < ntiles; tb++) {
        int kb = tb << 5;
        __syncthreads();
        for (int i = threadIdx.x; i < 32 * 32; i += 256) {
            int row = i >> 5, c4 = i & 31;
            ((float4*)Ks[row])[c4] =
                ((const float4*)(g_k + (size_t)(kb + row) * DMODEL + h * HDIM))[c4];
            ((float4*)Vs[row])[c4] =
                ((const float4*)(g_v + (size_t)(kb + row) * DMODEL + h * HDIM))[c4];
        }
        __syncthreads();
        int jmax = qi - kb + 1; if (jmax > 32) jmax = 32;
        for (int j = 0; j < jmax; j++) {
            float s = ql[0] * Ks[j][lane] + ql[1] * Ks[j][lane + 32] +
                      ql[2] * Ks[j][lane + 64] + ql[3] * Ks[j][lane + 96];
            #pragma unroll
            for (int o = 16; o; o >>= 1) s += __shfl_xor_sync(0xffffffffu, s, o);
            s *= 0.08838834764831845f;  // 1/sqrt(128)
            float mn = fmaxf(m, s);
            float corr = __expf(m - mn);
            float p = __expf(s - mn);
            l = l * corr + p;
            #pragma unroll
            for (int jj = 0; jj < 4; jj++)
                acc[jj] = acc[jj] * corr + p * Vs[j][lane + 32 * jj];
            m = mn;
        }
    }
    float inv = 1.f / l;
    #pragma unroll
    for (int jj = 0; jj < 4; jj++)
        g_n[(size_t)qi * DMODEL + h * HDIM + lane + 32 * jj] = acc[jj] * inv;
}

// ---------------- SGEMM: C[M,N] = A[M,K] * B[N,K]^T (+ epilogue) --------------
// 128x128x16 tiles, 256 threads, 8x8 microtile.
// epi: 0 = store; 1 = store res+acc; 2 = store relu(acc)^2
__global__ void __launch_bounds__(256, 2)
sgemm_kernel(const float* __restrict__ A, const float* __restrict__ B,
             float* __restrict__ C, const float* __restrict__ res,
             int M, int N, int K, int epi) {
    __shared__ float As[16][128];
    __shared__ float Bs[16][128];
    int tid = threadIdx.x;
    int tx = tid & 15, ty = tid >> 4;
    int m0 = blockIdx.y * 128, n0 = blockIdx.x * 128;
    int lr = tid >> 2;          // 0..63
    int lc = (tid & 3) << 2;    // 0,4,8,12
    const float* Ap = A + (size_t)(m0 + lr) * K + lc;
    const float* Bp = B + (size_t)(n0 + lr) * K + lc;
    float acc[8][8];
    #pragma unroll
    for (int i = 0; i < 8; i++)
        #pragma unroll
        for (int j = 0; j < 8; j++) acc[i][j] = 0.f;

    for (int k0 = 0; k0 < K; k0 += 16) {
        float4 a0 = *(const float4*)(Ap);
        float4 a1 = *(const float4*)(Ap + (size_t)64 * K);
        float4 b0 = *(const float4*)(Bp);
        float4 b1 = *(const float4*)(Bp + (size_t)64 * K);
        As[lc + 0][lr] = a0.x; As[lc + 1][lr] = a0.y; As[lc + 2][lr] = a0.z; As[lc + 3][lr] = a0.w;
        As[lc + 0][lr + 64] = a1.x; As[lc + 1][lr + 64] = a1.y; As[lc + 2][lr + 64] = a1.z; As[lc + 3][lr + 64] = a1.w;
        Bs[lc + 0][lr] = b0.x; Bs[lc + 1][lr] = b0.y; Bs[lc + 2][lr] = b0.z; Bs[lc + 3][lr] = b0.w;
        Bs[lc + 0][lr + 64] = b1.x; Bs[lc + 1][lr + 64] = b1.y; Bs[lc + 2][lr + 64] = b1.z; Bs[lc + 3][lr + 64] = b1.w;
        __syncthreads();
        #pragma unroll
        for (int kk = 0; kk < 16; kk++) {
            float a[8], b[8];
            *(float4*)(a)     = *(const float4*)&As[kk][ty * 8];
            *(float4*)(a + 4) = *(const float4*)&As[kk][ty * 8 + 4];
            *(float4*)(b)     = *(const float4*)&Bs[kk][tx * 8];
            *(float4*)(b + 4) = *(const float4*)&Bs[kk][tx * 8 + 4];
            #pragma unroll
            for (int i = 0; i < 8; i++)
                #pragma unroll
                for (int j = 0; j < 8; j++)
                    acc[i][j] = fmaf(a[i], b[j], acc[i][j]);
        }
        __syncthreads();
        Ap += 16; Bp += 16;
    }
    #pragma unroll
    for (int i = 0; i < 8; i++) {
        int m = m0 + ty * 8 + i;
        #pragma unroll
        for (int j = 0; j < 8; j++) {
            int n = n0 + tx * 8 + j;
            float vv = acc[i][j];
            if (epi == 1) vv += res[(size_t)m * N + n];
            if (epi == 2) { vv = fmaxf(vv, 0.f); vv = vv * vv; }
            C[(size_t)m * N + n] = vv;
        }
    }
}

// ---------------- lm_head GEMM: softcap + f32(bf16-rounded) store + lse ------
__global__ void __launch_bounds__(256, 2)
lmhead_kernel(const float* __restrict__ A, const float* __restrict__ B,
              float* __restrict__ out, const int* __restrict__ targets,
              int store) {
    const int N = VOCAB, K = DMODEL;
    __shared__ float As[16][128];
    __shared__ float Bs[16][128];
    __shared__ float red[128][17];
    int tid = threadIdx.x;
    int tx = tid & 15, ty = tid >> 4;
    int m0 = blockIdx.y * 128, n0 = blockIdx.x * 128;
    int lr = tid >> 2;
    int lc = (tid & 3) << 2;
    const float* Ap = A + (size_t)(m0 + lr) * K + lc;
    const float* Bp = B + (size_t)(n0 + lr) * K + lc;
    float acc[8][8];
    #pragma unroll
    for (int i = 0; i < 8; i++)
        #pragma unroll
        for (int j = 0; j < 8; j++) acc[i][j] = 0.f;

    for (int k0 = 0; k0 < K; k0 += 16) {
        float4 a0 = *(const float4*)(Ap);
        float4 a1 = *(const float4*)(Ap + (size_t)64 * K);
        float4 b0 = *(const float4*)(Bp);
        float4 b1 = *(const float4*)(Bp + (size_t)64 * K);
        As[lc + 0][lr] = a0.x; As[lc + 1][lr] = a0.y; As[lc + 2][lr] = a0.z; As[lc + 3][lr] = a0.w;
        As[lc + 0][lr + 64] = a1.x; As[lc + 1][lr + 64] = a1.y; As[lc + 2][lr + 64] = a1.z; As[lc + 3][lr + 64] = a1.w;
        Bs[lc + 0][lr] = b0.x; Bs[lc + 1][lr] = b0.y; Bs[lc + 2][lr] = b0.z; Bs[lc + 3][lr] = b0.w;
        Bs[lc + 0][lr + 64] = b1.x; Bs[lc + 1][lr + 64] = b1.y; Bs[lc + 2][lr + 64] = b1.z; Bs[lc + 3][lr + 64] = b1.w;
        __syncthreads();
        #pragma unroll
        for (int kk = 0; kk < 16; kk++) {
            float a[8], b[8];
            *(float4*)(a)     = *(const float4*)&As[kk][ty * 8];
            *(float4*)(a + 4) = *(const float4*)&As[kk][ty * 8 + 4];
            *(float4*)(b)     = *(const float4*)&Bs[kk][tx * 8];
            *(float4*)(b + 4) = *(const float4*)&Bs[kk][tx * 8 + 4];
            #pragma unroll
            for (int i = 0; i < 8; i++)
                #pragma unroll
                for (int j = 0; j < 8; j++)
                    acc[i][j] = fmaf(a[i], b[j], acc[i][j]);
        }
        __syncthreads();
        Ap += 16; Bp += 16;
    }
    // Epilogue: softcap; store f32 value rounded through bf16 (matches
    // reference logits.astype(bf16) compared in f32). Loss path uses the
    // UNROUNDED f32 value, matching the reference (loss computed pre-cast).
    float part[8];
    #pragma unroll
    for (int i = 0; i < 8; i++) part[i] = 0.f;
    #pragma unroll
    for (int i = 0; i < 8; i++) {
        int m = m0 + ty * 8 + i;
        int tg = targets[m];
        #pragma unroll
        for (int j = 0; j < 8; j++) {
            int n = n0 + tx * 8 + j;
            float vv = CAPV * tanhf(acc[i][j] * (1.f / CAPV));
            if (store)
                out[(size_t)m * N + n] = __bfloat162float(__float2bfloat16(vv));
            part[i] += __expf(vv - CAPV);
            if (n == tg) g_tl[m] = vv;
        }
    }
    #pragma unroll
    for (int i = 0; i < 8; i++) red[ty * 8 + i][tx] = part[i];
    __syncthreads();
    if (tid < 128) {
        float s = 0.f;
        #pragma unroll
        for (int j = 0; j < 16; j++) s += red[tid][j];
        atomicAdd(&g_rowsum[m0 + tid], s);
    }
}

__global__ void zero_kernel() {
    for (int i = threadIdx.x; i < SEQ; i += blockDim.x) g_rowsum[i] = 0.f;
}

__global__ void loss_kernel(float* out_f) {
    float s = 0.f;
    for (int t = threadIdx.x; t < SEQ; t += blockDim.x)
        s += CAPV + logf(g_rowsum[t]) - g_tl[t];
    s = blockReduceSum(s);
    if (threadIdx.x == 0 && out_f) out_f[0] = s / (float)SEQ;
}

// ---------------- launch ------------------------------------------------------
extern "C" void kernel_launch(void* const* d_in, const int* in_sizes, int n_in,
                              void* d_out, int out_size) {
    const int*   idx     = (const int*)d_in[0];
    const int*   targets = (const int*)d_in[1];
    const float* emb     = (const float*)d_in[2];
    const float* ln1_w   = (const float*)d_in[3];
    const float* qkv_w   = (const float*)d_in[4];
    const float* q_norm  = (const float*)d_in[5];
    const float* k_norm  = (const float*)d_in[6];
    const float* proj_w  = (const float*)d_in[7];
    const float* ln2_w   = (const float*)d_in[8];
    const float* fc1_w   = (const float*)d_in[9];
    const float* fc2_w   = (const float*)d_in[10];
    const float* lnf_w   = (const float*)d_in[11];
    const float* lm_w    = (const float*)d_in[12];

    float *p_x, *p_n, *p_big;
    cudaGetSymbolAddress((void**)&p_x, g_x);
    cudaGetSymbolAddress((void**)&p_n, g_n);
    cudaGetSymbolAddress((void**)&p_big, g_big);

    const long long NTV = (long long)SEQ * VOCAB;
    int store_logits = ((long long)out_size >= NTV) ? 1 : 0;

    embed_kernel<<<SEQ, 256>>>(idx, emb);

    for (int l = 0; l < LNUM; l++) {
        const float* l1 = ln1_w + (size_t)l * DMODEL;
        const float* qk = qkv_w + (size_t)l * 3 * DMODEL * DMODEL;
        const float* qn = q_norm + (size_t)l * HDIM;
        const float* kn = k_norm + (size_t)l * HDIM;
        const float* pw = proj_w + (size_t)l * DMODEL * DMODEL;
        const float* l2 = ln2_w + (size_t)l * DMODEL;
        const float* f1 = fc1_w + (size_t)l * FFDIM * DMODEL;
        const float* f2 = fc2_w + (size_t)l * DMODEL * FFDIM;

        rmsnorm_kernel<<<SEQ, 256>>>(p_x, l1, p_n);
        {
            dim3 g((3 * DMODEL) / 128, SEQ / 128);
            sgemm_kernel<<<g, 256>>>(p_n, qk, p_big, nullptr,
                                     SEQ, 3 * DMODEL, DMODEL, 0);
        }
        {
            dim3 g(SEQ, NHEAD);
            rope_kernel<<<g, HDIM>>>(p_big, qn, kn);
        }
        {
            dim3 g(SEQ / 8, NHEAD);
            attn_kernel<<<g, 256>>>();
        }
        {
            dim3 g(DMODEL / 128, SEQ / 128);
            sgemm_kernel<<<g, 256>>>(p_n, pw, p_x, p_x,
                                     SEQ, DMODEL, DMODEL, 1);
        }
        rmsnorm_kernel<<<SEQ, 256>>>(p_x, l2, p_n);
        {
            dim3 g(FFDIM / 128, SEQ / 128);
            sgemm_kernel<<<g, 256>>>(p_n, f1, p_big, nullptr,
                                     SEQ, FFDIM, DMODEL, 2);
        }
        {
            dim3 g(DMODEL / 128, SEQ / 128);
            sgemm_kernel<<<g, 256>>>(p_big, f2, p_x, p_x,
                                     SEQ, DMODEL, FFDIM, 1);
        }
    }

    rmsnorm_kernel<<<SEQ, 256>>>(p_x, lnf_w, p_n);
    zero_kernel<<<1, 256>>>();
    {
        dim3 g(VOCAB / 128, SEQ / 128);
        lmhead_kernel<<<g, 256>>>(p_n, lm_w, (float*)d_out, targets,
                                  store_logits);
    }
    if (store_logits) {
        float* lossp =
            ((long long)out_size > NTV) ? ((float*)d_out + NTV) : nullptr;
        loss_kernel<<<1, 256>>>(lossp);
    } else {
        loss_kernel<<<1, 256>>>((float*)d_out);
    }
}

// round 3
// speedup vs baseline: 1.5110x; 1.5110x over previous
#include <cuda_runtime.h>
#include <cuda_bf16.h>
#include <math.h>
#include <stdint.h>

// Model dims
#define LNUM 12
#define DMODEL 768
#define NHEAD 6
#define HDIM 128
#define FFDIM 3072
#define VOCAB 65536
#define SEQ 2048
#define EPSV 1e-5f
#define CAPV 30.0f

#define NQKV (12LL * 2304 * 768)
#define NPROJ (12LL * 768 * 768)
#define NFC1 (12LL * 3072 * 768)
#define NFC2 (12LL * 768 * 3072)
#define NLM (65536LL * 768)

// ---------------- scratch (static device arrays; no allocation) -------------
__device__ float g_x[SEQ * DMODEL];     // residual stream (f32)
__device__ float g_big[SEQ * FFDIM];    // qkv out (2304<=3072) f32
__device__ float g_q[SEQ * DMODEL];
__device__ float g_k[SEQ * DMODEL];
__device__ float g_v[SEQ * DMODEL];
__device__ float g_rowsum[SEQ];
__device__ float g_tl[SEQ];

// split-precision weight planes (bf16 hi/lo)
__device__ __align__(16) __nv_bfloat16 w_qkv_h[NQKV], w_qkv_l[NQKV];
__device__ __align__(16) __nv_bfloat16 w_proj_h[NPROJ], w_proj_l[NPROJ];
__device__ __align__(16) __nv_bfloat16 w_fc1_h[NFC1], w_fc1_l[NFC1];
__device__ __align__(16) __nv_bfloat16 w_fc2_h[NFC2], w_fc2_l[NFC2];
__device__ __align__(16) __nv_bfloat16 w_lm_h[NLM], w_lm_l[NLM];

// activation planes
__device__ __align__(16) __nv_bfloat16 an_h[SEQ * DMODEL], an_l[SEQ * DMODEL];
__device__ __align__(16) __nv_bfloat16 ah_h[SEQ * FFDIM], ah_l[SEQ * FFDIM];

// ---------------- helpers ----------------------------------------------------
__device__ __forceinline__ void split2(float v, __nv_bfloat16& h, __nv_bfloat16& l) {
    h = __float2bfloat16(v);
    l = __float2bfloat16(v - __bfloat162float(h));
}

__device__ __forceinline__ float blockReduceSum(float v) {
    __shared__ float sh[32];
    __syncthreads();
    int lane = threadIdx.x & 31, wid = threadIdx.x >> 5;
    #pragma unroll
    for (int o = 16; o; o >>= 1) v += __shfl_xor_sync(0xffffffffu, v, o);
    if (lane == 0) sh[wid] = v;
    __syncthreads();
    int nw = blockDim.x >> 5;
    v = (threadIdx.x < nw) ? sh[threadIdx.x] : 0.f;
    if (wid == 0) {
        #pragma unroll
        for (int o = 16; o; o >>= 1) v += __shfl_xor_sync(0xffffffffu, v, o);
        if (lane == 0) sh[0] = v;
    }
    __syncthreads();
    return sh[0];
}

__device__ __forceinline__ void ldsm4(uint32_t (&r)[4], uint32_t addr) {
    asm volatile("ldmatrix.sync.aligned.m8n8.x4.shared.b16 {%0,%1,%2,%3},[%4];"
                 : "=r"(r[0]), "=r"(r[1]), "=r"(r[2]), "=r"(r[3]) : "r"(addr));
}

__device__ __forceinline__ void mma_bf16(float (&d)[4], const uint32_t (&a)[4],
                                         uint32_t b0, uint32_t b1) {
    asm volatile(
        "mma.sync.aligned.m16n8k16.row.col.f32.bf16.bf16.f32 "
        "{%0,%1,%2,%3},{%4,%5,%6,%7},{%8,%9},{%0,%1,%2,%3};"
        : "+f"(d[0]), "+f"(d[1]), "+f"(d[2]), "+f"(d[3])
        : "r"(a[0]), "r"(a[1]), "r"(a[2]), "r"(a[3]), "r"(b0), "r"(b1));
}

// ---------------- weight split kernel -----------------------------------------
__global__ void split_kernel(const float4* __restrict__ s,
                             __nv_bfloat16* __restrict__ h,
                             __nv_bfloat16* __restrict__ l, long long n4) {
    long long i = blockIdx.x * (long long)blockDim.x + threadIdx.x;
    long long stride = gridDim.x * (long long)blockDim.x;
    for (; i < n4; i += stride) {
        float4 v = s[i];
        long long o = i * 4;
        split2(v.x, h[o], l[o]);
        split2(v.y, h[o + 1], l[o + 1]);
        split2(v.z, h[o + 2], l[o + 2]);
        split2(v.w, h[o + 3], l[o + 3]);
    }
}

// ---------------- elementwise kernels ----------------------------------------
__global__ void embed_kernel(const int* __restrict__ idx,
                             const float* __restrict__ emb) {
    int t = blockIdx.x;
    int row = idx[t];
    const float* src = emb + (size_t)row * DMODEL;
    for (int i = threadIdx.x; i < DMODEL; i += blockDim.x)
        g_x[t * DMODEL + i] = src[i];
}

// rmsnorm -> split bf16 planes
__global__ void rmsnorm_kernel(const float* __restrict__ x,
                               const float* __restrict__ w) {
    int t = blockIdx.x;
    const float* xr = x + (size_t)t * DMODEL;
    float s = 0.f;
    for (int i = threadIdx.x; i < DMODEL; i += blockDim.x) {
        float v = xr[i];
        s += v * v;
    }
    s = blockReduceSum(s);
    float r = rsqrtf(s / (float)DMODEL + EPSV);
    for (int i = threadIdx.x; i < DMODEL; i += blockDim.x) {
        float v = xr[i] * r * w[i];
        split2(v, an_h[t * DMODEL + i], an_l[t * DMODEL + i]);
    }
}

// Per (t, head): q/k head-RMSNorm + RoPE; reads qkv (f32) from g_big
__global__ void rope_kernel(const float* __restrict__ qkv,
                            const float* __restrict__ qw,
                            const float* __restrict__ kw) {
    int t = blockIdx.x, h = blockIdx.y, d = threadIdx.x;
    const float* base = qkv + (size_t)t * (3 * DMODEL);
    float qd = base[h * HDIM + d];
    float kd = base[DMODEL + h * HDIM + d];
    float vd = base[2 * DMODEL + h * HDIM + d];
    float qs = blockReduceSum(qd * qd);
    float ks = blockReduceSum(kd * kd);
    float qn = qd * rsqrtf(qs / (float)HDIM + EPSV) * qw[d];
    float kn = kd * rsqrtf(ks / (float)HDIM + EPSV) * kw[d];
    __shared__ float sq[HDIM], sk[HDIM];
    sq[d] = qn; sk[d] = kn;
    __syncthreads();
    float expo = -(float)((d & 63) * 2) / (float)HDIM;
    float invf = expf(expo * logf(10000.f));
    float ang = (float)t * invf;
    float c = cosf(ang), s = sinf(ang);
    float qr = (d < 64) ? -sq[d + 64] : sq[d - 64];
    float kr = (d < 64) ? -sk[d + 64] : sk[d - 64];
    size_t oidx = (size_t)t * DMODEL + h * HDIM + d;
    g_q[oidx] = qn * c + qr * s;
    g_k[oidx] = kn * c + kr * s;
    g_v[oidx] = vd;
}

// ---------------- attention: warp-per-query, online softmax ------------------
__global__ void attn_kernel() {
    const int h = blockIdx.y;
    const int qbase = blockIdx.x * 8;
    const int warp = threadIdx.x >> 5, lane = threadIdx.x & 31;
    const int qi = qbase + warp;
    __shared__ float Ks[32][HDIM];
    __shared__ float Vs[32][HDIM];
    float ql[4];
    #pragma unroll
    for (int j = 0; j < 4; j++)
        ql[j] = g_q[(size_t)qi * DMODEL + h * HDIM + lane + 32 * j];
    float m = -1e30f, l = 0.f;
    float acc[4] = {0.f, 0.f, 0.f, 0.f};
    int ntiles = (qbase + 8 + 31) >> 5;
    for (int tb = 0; tb < ntiles; tb++) {
        int kb = tb << 5;
        __syncthreads();
        for (int i = threadIdx.x; i < 32 * 32; i += 256) {
            int row = i >> 5, c4 = i & 31;
            ((float4*)Ks[row])[c4] =
                ((const float4*)(g_k + (size_t)(kb + row) * DMODEL + h * HDIM))[c4];
            ((float4*)Vs[row])[c4] =
                ((const float4*)(g_v + (size_t)(kb + row) * DMODEL + h * HDIM))[c4];
        }
        __syncthreads();
        int jmax = qi - kb + 1; if (jmax > 32) jmax = 32;
        for (int j = 0; j < jmax; j++) {
            float s = ql[0] * Ks[j][lane] + ql[1] * Ks[j][lane + 32] +
                      ql[2] * Ks[j][lane + 64] + ql[3] * Ks[j][lane + 96];
            #pragma unroll
            for (int o = 16; o; o >>= 1) s += __shfl_xor_sync(0xffffffffu, s, o);
            s *= 0.08838834764831845f;
            float mn = fmaxf(m, s);
            float corr = __expf(m - mn);
            float p = __expf(s - mn);
            l = l * corr + p;
            #pragma unroll
            for (int jj = 0; jj < 4; jj++)
                acc[jj] = acc[jj] * corr + p * Vs[j][lane + 32 * jj];
            m = mn;
        }
    }
    float inv = 1.f / l;
    #pragma unroll
    for (int jj = 0; jj < 4; jj++) {
        size_t o = (size_t)qi * DMODEL + h * HDIM + lane + 32 * jj;
        split2(acc[jj] * inv, an_h[o], an_l[o]);
    }
}

// ---------------- bf16x3 tensor-core GEMM ------------------------------------
// C[M,N] = A[M,K] * B[N,K]^T, A/B given as bf16 hi/lo planes, f32 accumulate.
// Block 128x128, BK=32, 8 warps of 64x32. epi: 0=f32 store, 1=+res f32,
// 2 = relu^2 -> split bf16 planes Oh/Ol.
__global__ void __launch_bounds__(256, 1)
gemm3_kernel(const __nv_bfloat16* __restrict__ Ah, const __nv_bfloat16* __restrict__ Al,
             const __nv_bfloat16* __restrict__ Bh, const __nv_bfloat16* __restrict__ Bl,
             float* __restrict__ C, const float* __restrict__ res,
             __nv_bfloat16* __restrict__ Oh, __nv_bfloat16* __restrict__ Ol,
             int M, int N, int K, int epi) {
    __shared__ __align__(16) __nv_bfloat16 sAh[128 * 40];
    __shared__ __align__(16) __nv_bfloat16 sAl[128 * 40];
    __shared__ __align__(16) __nv_bfloat16 sBh[128 * 40];
    __shared__ __align__(16) __nv_bfloat16 sBl[128 * 40];
    const int tid = threadIdx.x, lane = tid & 31, wid = tid >> 5;
    const int wm = wid >> 2, wn = wid & 3;
    const int m0 = blockIdx.x * 128, n0 = blockIdx.y * 128;
    const int ldr = tid >> 2, ldc = tid & 3;
    const __nv_bfloat16* gAh = Ah + (size_t)(m0 + ldr) * K + ldc * 8;
    const __nv_bfloat16* gAl = Al + (size_t)(m0 + ldr) * K + ldc * 8;
    const __nv_bfloat16* gBh = Bh + (size_t)(n0 + ldr) * K + ldc * 8;
    const __nv_bfloat16* gBl = Bl + (size_t)(n0 + ldr) * K + ldc * 8;
    const size_t rstep = (size_t)64 * K;
    uint4 v[8];
    v[0] = *(const uint4*)(gAh); v[1] = *(const uint4*)(gAh + rstep);
    v[2] = *(const uint4*)(gAl); v[3] = *(const uint4*)(gAl + rstep);
    v[4] = *(const uint4*)(gBh); v[5] = *(const uint4*)(gBh + rstep);
    v[6] = *(const uint4*)(gBl); v[7] = *(const uint4*)(gBl + rstep);
    float acc[4][4][4];
    #pragma unroll
    for (int a = 0; a < 4; a++)
        #pragma unroll
        for (int b = 0; b < 4; b++)
            #pragma unroll
            for (int c = 0; c < 4; c++) acc[a][b][c] = 0.f;
    const int s0 = ldr * 40 + ldc * 8, s1 = (ldr + 64) * 40 + ldc * 8;
    const uint32_t bAh = (uint32_t)__cvta_generic_to_shared(sAh);
    const uint32_t bAl = (uint32_t)__cvta_generic_to_shared(sAl);
    const uint32_t bBh = (uint32_t)__cvta_generic_to_shared(sBh);
    const uint32_t bBl = (uint32_t)__cvta_generic_to_shared(sBl);

    for (int k0 = 0; k0 < K; k0 += 32) {
        *(uint4*)(sAh + s0) = v[0]; *(uint4*)(sAh + s1) = v[1];
        *(uint4*)(sAl + s0) = v[2]; *(uint4*)(sAl + s1) = v[3];
        *(uint4*)(sBh + s0) = v[4]; *(uint4*)(sBh + s1) = v[5];
        *(uint4*)(sBl + s0) = v[6]; *(uint4*)(sBl + s1) = v[7];
        __syncthreads();
        if (k0 + 32 < K) {
            gAh += 32; gAl += 32; gBh += 32; gBl += 32;
            v[0] = *(const uint4*)(gAh); v[1] = *(const uint4*)(gAh + rstep);
            v[2] = *(const uint4*)(gAl); v[3] = *(const uint4*)(gAl + rstep);
            v[4] = *(const uint4*)(gBh); v[5] = *(const uint4*)(gBh + rstep);
            v[6] = *(const uint4*)(gBl); v[7] = *(const uint4*)(gBl + rstep);
        }
        #pragma unroll
        for (int kh = 0; kh < 2; kh++) {
            uint32_t a_h[4][4], a_l[4][4], b_h[2][4], b_l[2][4];
            const int acol = kh * 16 + ((lane >> 4) << 3);
            #pragma unroll
            for (int mt = 0; mt < 4; mt++) {
                int arow = wm * 64 + mt * 16 + (lane & 15);
                uint32_t off = (uint32_t)(arow * 40 + acol) * 2;
                ldsm4(a_h[mt], bAh + off);
                ldsm4(a_l[mt], bAl + off);
            }
            const int brow = wn * 32 + ((lane >> 4) << 3) + (lane & 7);
            const int bcol = kh * 16 + (((lane >> 3) & 1) << 3);
            #pragma unroll
            for (int p = 0; p < 2; p++) {
                uint32_t off = (uint32_t)((brow + p * 16) * 40 + bcol) * 2;
                ldsm4(b_h[p], bBh + off);
                ldsm4(b_l[p], bBl + off);
            }
            #pragma unroll
            for (int mt = 0; mt < 4; mt++)
                #pragma unroll
                for (int nt = 0; nt < 4; nt++) {
                    int p = nt >> 1, s = (nt & 1) * 2;
                    mma_bf16(acc[mt][nt], a_h[mt], b_h[p][s], b_h[p][s + 1]);
                    mma_bf16(acc[mt][nt], a_h[mt], b_l[p][s], b_l[p][s + 1]);
                    mma_bf16(acc[mt][nt], a_l[mt], b_h[p][s], b_h[p][s + 1]);
                }
        }
        __syncthreads();
    }
    #pragma unroll
    for (int mt = 0; mt < 4; mt++)
        #pragma unroll
        for (int nt = 0; nt < 4; nt++)
            #pragma unroll
            for (int r = 0; r < 4; r++) {
                int row = m0 + wm * 64 + mt * 16 + (lane >> 2) + (r >> 1) * 8;
                int col = n0 + wn * 32 + nt * 8 + (lane & 3) * 2 + (r & 1);
                float vv = acc[mt][nt][r];
                size_t o = (size_t)row * N + col;
                if (epi == 0) C[o] = vv;
                else if (epi == 1) C[o] = vv + res[o];
                else {
                    vv = fmaxf(vv, 0.f); vv = vv * vv;
                    split2(vv, Oh[o], Ol[o]);
                }
            }
}

// ---------------- lm_head: bf16x3 GEMM + softcap/store/lse epilogue ----------
__global__ void __launch_bounds__(256, 1)
lmhead_kernel(const __nv_bfloat16* __restrict__ Ah, const __nv_bfloat16* __restrict__ Al,
              const __nv_bfloat16* __restrict__ Bh, const __nv_bfloat16* __restrict__ Bl,
              float* __restrict__ out, const int* __restrict__ targets, int store) {
    const int N = VOCAB, K = DMODEL;
    __shared__ __align__(16) __nv_bfloat16 sAh[128 * 40];
    __shared__ __align__(16) __nv_bfloat16 sAl[128 * 40];
    __shared__ __align__(16) __nv_bfloat16 sBh[128 * 40];
    __shared__ __align__(16) __nv_bfloat16 sBl[128 * 40];
    const int tid = threadIdx.x, lane = tid & 31, wid = tid >> 5;
    const int wm = wid >> 2, wn = wid & 3;
    const int m0 = blockIdx.x * 128, n0 = blockIdx.y * 128;
    const int ldr = tid >> 2, ldc = tid & 3;
    const __nv_bfloat16* gAh = Ah + (size_t)(m0 + ldr) * K + ldc * 8;
    const __nv_bfloat16* gAl = Al + (size_t)(m0 + ldr) * K + ldc * 8;
    const __nv_bfloat16* gBh = Bh + (size_t)(n0 + ldr) * K + ldc * 8;
    const __nv_bfloat16* gBl = Bl + (size_t)(n0 + ldr) * K + ldc * 8;
    const size_t rstep = (size_t)64 * K;
    uint4 v[8];
    v[0] = *(const uint4*)(gAh); v[1] = *(const uint4*)(gAh + rstep);
    v[2] = *(const uint4*)(gAl); v[3] = *(const uint4*)(gAl + rstep);
    v[4] = *(const uint4*)(gBh); v[5] = *(const uint4*)(gBh + rstep);
    v[6] = *(const uint4*)(gBl); v[7] = *(const uint4*)(gBl + rstep);
    float acc[4][4][4];
    #pragma unroll
    for (int a = 0; a < 4; a++)
        #pragma unroll
        for (int b = 0; b < 4; b++)
            #pragma unroll
            for (int c = 0; c < 4; c++) acc[a][b][c] = 0.f;
    const int s0 = ldr * 40 + ldc * 8, s1 = (ldr + 64) * 40 + ldc * 8;
    const uint32_t bAh = (uint32_t)__cvta_generic_to_shared(sAh);
    const uint32_t bAl = (uint32_t)__cvta_generic_to_shared(sAl);
    const uint32_t bBh = (uint32_t)__cvta_generic_to_shared(sBh);
    const uint32_t bBl = (uint32_t)__cvta_generic_to_shared(sBl);

    for (int k0 = 0; k0 < K; k0 += 32) {
        *(uint4*)(sAh + s0) = v[0]; *(uint4*)(sAh + s1) = v[1];
        *(uint4*)(sAl + s0) = v[2]; *(uint4*)(sAl + s1) = v[3];
        *(uint4*)(sBh + s0) = v[4]; *(uint4*)(sBh + s1) = v[5];
        *(uint4*)(sBl + s0) = v[6]; *(uint4*)(sBl + s1) = v[7];
        __syncthreads();
        if (k0 + 32 < K) {
            gAh += 32; gAl += 32; gBh += 32; gBl += 32;
            v[0] = *(const uint4*)(gAh); v[1] = *(const uint4*)(gAh + rstep);
            v[2] = *(const uint4*)(gAl); v[3] = *(const uint4*)(gAl + rstep);
            v[4] = *(const uint4*)(gBh); v[5] = *(const uint4*)(gBh + rstep);
            v[6] = *(const uint4*)(gBl); v[7] = *(const uint4*)(gBl + rstep);
        }
        #pragma unroll
        for (int kh = 0; kh < 2; kh++) {
            uint32_t a_h[4][4], a_l[4][4], b_h[2][4], b_l[2][4];
            const int acol = kh * 16 + ((lane >> 4) << 3);
            #pragma unroll
            for (int mt = 0; mt < 4; mt++) {
                int arow = wm * 64 + mt * 16 + (lane & 15);
                uint32_t off = (uint32_t)(arow * 40 + acol) * 2;
                ldsm4(a_h[mt], bAh + off);
                ldsm4(a_l[mt], bAl + off);
            }
            const int brow = wn * 32 + ((lane >> 4) << 3) + (lane & 7);
            const int bcol = kh * 16 + (((lane >> 3) & 1) << 3);
            #pragma unroll
            for (int p = 0; p < 2; p++) {
                uint32_t off = (uint32_t)((brow + p * 16) * 40 + bcol) * 2;
                ldsm4(b_h[p], bBh + off);
                ldsm4(b_l[p], bBl + off);
            }
            #pragma unroll
            for (int mt = 0; mt < 4; mt++)
                #pragma unroll
                for (int nt = 0; nt < 4; nt++) {
                    int p = nt >> 1, s = (nt & 1) * 2;
                    mma_bf16(acc[mt][nt], a_h[mt], b_h[p][s], b_h[p][s + 1]);
                    mma_bf16(acc[mt][nt], a_h[mt], b_l[p][s], b_l[p][s + 1]);
                    mma_bf16(acc[mt][nt], a_l[mt], b_h[p][s], b_h[p][s + 1]);
                }
        }
        __syncthreads();
    }
    // epilogue: softcap, bf16-rounded f32 store, per-row sumexp, target logit
    float ps[8];
    #pragma unroll
    for (int i = 0; i < 8; i++) ps[i] = 0.f;
    #pragma unroll
    for (int mt = 0; mt < 4; mt++)
        #pragma unroll
        for (int nt = 0; nt < 4; nt++)
            #pragma unroll
            for (int r = 0; r < 4; r++) {
                int row = m0 + wm * 64 + mt * 16 + (lane >> 2) + (r >> 1) * 8;
                int col = n0 + wn * 32 + nt * 8 + (lane & 3) * 2 + (r & 1);
                float vv = CAPV * tanhf(acc[mt][nt][r] * (1.f / CAPV));
                if (store)
                    out[(size_t)row * N + col] =
                        __bfloat162float(__float2bfloat16(vv));
                ps[mt * 2 + (r >> 1)] += __expf(vv - CAPV);
                if (col == targets[row]) g_tl[row] = vv;
            }
    #pragma unroll
    for (int i = 0; i < 8; i++) {
        ps[i] += __shfl_xor_sync(0xffffffffu, ps[i], 1);
        ps[i] += __shfl_xor_sync(0xffffffffu, ps[i], 2);
    }
    float* red = (float*)sAh;  // [128][4], reuse smem
    if ((lane & 3) == 0) {
        #pragma unroll
        for (int mt = 0; mt < 4; mt++)
            #pragma unroll
            for (int hh = 0; hh < 2; hh++) {
                int rl = wm * 64 + mt * 16 + (lane >> 2) + hh * 8;
                red[rl * 4 + wn] = ps[mt * 2 + hh];
            }
    }
    __syncthreads();
    if (tid < 128) {
        float s = red[tid * 4] + red[tid * 4 + 1] + red[tid * 4 + 2] + red[tid * 4 + 3];
        atomicAdd(&g_rowsum[m0 + tid], s);
    }
}

__global__ void zero_kernel() {
    for (int i = threadIdx.x; i < SEQ; i += blockDim.x) g_rowsum[i] = 0.f;
}

__global__ void loss_kernel(float* out_f) {
    float s = 0.f;
    for (int t = threadIdx.x; t < SEQ; t += blockDim.x)
        s += CAPV + logf(g_rowsum[t]) - g_tl[t];
    s = blockReduceSum(s);
    if (threadIdx.x == 0 && out_f) out_f[0] = s / (float)SEQ;
}

// ---------------- launch ------------------------------------------------------
extern "C" void kernel_launch(void* const* d_in, const int* in_sizes, int n_in,
                              void* d_out, int out_size) {
    const int*   idx     = (const int*)d_in[0];
    const int*   targets = (const int*)d_in[1];
    const float* emb     = (const float*)d_in[2];
    const float* ln1_w   = (const float*)d_in[3];
    const float* qkv_w   = (const float*)d_in[4];
    const float* q_norm  = (const float*)d_in[5];
    const float* k_norm  = (const float*)d_in[6];
    const float* proj_w  = (const float*)d_in[7];
    const float* ln2_w   = (const float*)d_in[8];
    const float* fc1_w   = (const float*)d_in[9];
    const float* fc2_w   = (const float*)d_in[10];
    const float* lnf_w   = (const float*)d_in[11];
    const float* lm_w    = (const float*)d_in[12];

    float *p_x, *p_big;
    cudaGetSymbolAddress((void**)&p_x, g_x);
    cudaGetSymbolAddress((void**)&p_big, g_big);
    __nv_bfloat16 *pqh, *pql, *pph, *ppl, *pf1h, *pf1l, *pf2h, *pf2l, *plmh, *plml;
    __nv_bfloat16 *panh, *panl, *pahh, *pahl;
    cudaGetSymbolAddress((void**)&pqh, w_qkv_h);  cudaGetSymbolAddress((void**)&pql, w_qkv_l);
    cudaGetSymbolAddress((void**)&pph, w_proj_h); cudaGetSymbolAddress((void**)&ppl, w_proj_l);
    cudaGetSymbolAddress((void**)&pf1h, w_fc1_h); cudaGetSymbolAddress((void**)&pf1l, w_fc1_l);
    cudaGetSymbolAddress((void**)&pf2h, w_fc2_h); cudaGetSymbolAddress((void**)&pf2l, w_fc2_l);
    cudaGetSymbolAddress((void**)&plmh, w_lm_h);  cudaGetSymbolAddress((void**)&plml, w_lm_l);
    cudaGetSymbolAddress((void**)&panh, an_h);    cudaGetSymbolAddress((void**)&panl, an_l);
    cudaGetSymbolAddress((void**)&pahh, ah_h);    cudaGetSymbolAddress((void**)&pahl, ah_l);

    const long long NTV = (long long)SEQ * VOCAB;
    int store_logits = ((long long)out_size >= NTV) ? 1 : 0;

    // split weights (recomputed each launch; deterministic)
    split_kernel<<<4096, 256>>>((const float4*)qkv_w, pqh, pql, NQKV / 4);
    split_kernel<<<4096, 256>>>((const float4*)proj_w, pph, ppl, NPROJ / 4);
    split_kernel<<<4096, 256>>>((const float4*)fc1_w, pf1h, pf1l, NFC1 / 4);
    split_kernel<<<4096, 256>>>((const float4*)fc2_w, pf2h, pf2l, NFC2 / 4);
    split_kernel<<<8192, 256>>>((const float4*)lm_w, plmh, plml, NLM / 4);

    embed_kernel<<<SEQ, 256>>>(idx, emb);

    for (int l = 0; l < LNUM; l++) {
        const float* l1 = ln1_w + (size_t)l * DMODEL;
        const float* qn = q_norm + (size_t)l * HDIM;
        const float* kn = k_norm + (size_t)l * HDIM;
        const float* l2 = ln2_w + (size_t)l * DMODEL;
        __nv_bfloat16* qkh = pqh + (size_t)l * 2304 * 768;
        __nv_bfloat16* qkl = pql + (size_t)l * 2304 * 768;
        __nv_bfloat16* pwh = pph + (size_t)l * 768 * 768;
        __nv_bfloat16* pwl = ppl + (size_t)l * 768 * 768;
        __nv_bfloat16* f1h = pf1h + (size_t)l * 3072 * 768;
        __nv_bfloat16* f1l = pf1l + (size_t)l * 3072 * 768;
        __nv_bfloat16* f2h = pf2h + (size_t)l * 768 * 3072;
        __nv_bfloat16* f2l = pf2l + (size_t)l * 768 * 3072;

        rmsnorm_kernel<<<SEQ, 256>>>(p_x, l1);
        gemm3_kernel<<<dim3(SEQ / 128, (3 * DMODEL) / 128), 256>>>(
            panh, panl, qkh, qkl, p_big, nullptr, nullptr, nullptr,
            SEQ, 3 * DMODEL, DMODEL, 0);
        {
            dim3 g(SEQ, NHEAD);
            rope_kernel<<<g, HDIM>>>(p_big, qn, kn);
        }
        {
            dim3 g(SEQ / 8, NHEAD);
            attn_kernel<<<g, 256>>>();
        }
        gemm3_kernel<<<dim3(SEQ / 128, DMODEL / 128), 256>>>(
            panh, panl, pwh, pwl, p_x, p_x, nullptr, nullptr,
            SEQ, DMODEL, DMODEL, 1);
        rmsnorm_kernel<<<SEQ, 256>>>(p_x, l2);
        gemm3_kernel<<<dim3(SEQ / 128, FFDIM / 128), 256>>>(
            panh, panl, f1h, f1l, nullptr, nullptr, pahh, pahl,
            SEQ, FFDIM, DMODEL, 2);
        gemm3_kernel<<<dim3(SEQ / 128, DMODEL / 128), 256>>>(
            pahh, pahl, f2h, f2l, p_x, p_x, nullptr, nullptr,
            SEQ, DMODEL, FFDIM, 1);
    }

    rmsnorm_kernel<<<SEQ, 256>>>(p_x, lnf_w);
    zero_kernel<<<1, 256>>>();
    lmhead_kernel<<<dim3(SEQ / 128, VOCAB / 128), 256>>>(
        panh, panl, plmh, plml, (float*)d_out, targets, store_logits);
    if (store_logits) {
        float* lossp =
            ((long long)out_size > NTV) ? ((float*)d_out + NTV) : nullptr;
        loss_kernel<<<1, 256>>>(lossp);
    } else {
        loss_kernel<<<1, 256>>>((float*)d_out);
    }
}